// round 3
// baseline (speedup 1.0000x reference)
#include <cuda_runtime.h>

// Pooling_83141976916902: degenerate softmax gate => pure sorted segment-sum.
//   out[g, :] = sum_{n : batch[n]==g} x[n, :],  N=1e6, C=128.
//
// R3 vs R2 (90.6us, DRAM 75.0%, occ 58.2%):
//  - int32 indexing (fits: N*32 < 2^31) -> fewer regs, fewer IMADs
//  - __launch_bounds__(128,12): regs<=42 -> 12 blocks/SM, grid 148*12 single
//    wave, 48 resident warps/SM (aggregate MLP up ~30%)
//  - __ldcs streaming loads for x (read-once; keep L2 for output atomics)
//  - dual accumulators halve the FADD dependency chain per load batch

#define CCH 128

__global__ void zero_out_kernel(float4* __restrict__ out, int n4) {
    int i = blockIdx.x * blockDim.x + threadIdx.x;
    if (i < n4) out[i] = make_float4(0.f, 0.f, 0.f, 0.f);
}

__device__ __forceinline__ int seg_at(const void* batch, int n, bool is64) {
    if (is64) return (int)__ldg(((const long long*)batch) + n);
    return __ldg(((const int*)batch) + n);
}

__device__ __forceinline__ void red_add_v4(float* addr, float4 v) {
    asm volatile("red.global.add.v4.f32 [%0], {%1, %2, %3, %4};"
                 :: "l"(addr), "f"(v.x), "f"(v.y), "f"(v.z), "f"(v.w)
                 : "memory");
}

__global__ __launch_bounds__(128, 12) void seg_sum_kernel(
    const float4* __restrict__ x4,     // N rows x 32 float4
    const void*   __restrict__ batch,  // int32 or int64, sorted
    float*        __restrict__ out,    // [G * 128]
    int N, int nwarp_total)
{
    // dtype probe: odd int32 index mid-array. int64 -> high word == 0;
    // int32 -> sorted mid segment id != 0. In-bounds either way.
    const int probe = ((N >> 1) | 1);
    const bool is64 = (__ldg(((const int*)batch) + probe) == 0);

    const int gwarp = (blockIdx.x * blockDim.x + threadIdx.x) >> 5;
    const int lane  = threadIdx.x & 31;

    const int chunk = (N + nwarp_total - 1) / nwarp_total;
    int n0 = gwarp * chunk;
    int n1 = n0 + chunk;
    if (n1 > N) n1 = N;
    if (n0 >= n1) return;

    float4 accA = make_float4(0.f, 0.f, 0.f, 0.f);
    float4 accB = make_float4(0.f, 0.f, 0.f, 0.f);
    int cur = seg_at(batch, n0, is64);

    // per-lane streaming pointer, advanced by 8 rows per iteration
    const float4* p = x4 + n0 * 32 + lane;

    int n = n0;
    constexpr int U = 8;

    for (; n + U <= n1; n += U, p += U * 32) {
        float4 v[U];
        #pragma unroll
        for (int u = 0; u < U; u++)
            v[u] = __ldcs(p + u * 32);             // U independent streaming loads
        #pragma unroll
        for (int u = 0; u < U; u += 2) {
            int s0 = seg_at(batch, n + u, is64);   // L1 broadcast hits
            if (s0 != cur) {
                float4 m = make_float4(accA.x + accB.x, accA.y + accB.y,
                                       accA.z + accB.z, accA.w + accB.w);
                red_add_v4(out + cur * CCH + lane * 4, m);
                accA = make_float4(0.f, 0.f, 0.f, 0.f);
                accB = make_float4(0.f, 0.f, 0.f, 0.f);
                cur = s0;
            }
            accA.x += v[u].x; accA.y += v[u].y;
            accA.z += v[u].z; accA.w += v[u].w;

            int s1 = seg_at(batch, n + u + 1, is64);
            if (s1 != cur) {
                float4 m = make_float4(accA.x + accB.x, accA.y + accB.y,
                                       accA.z + accB.z, accA.w + accB.w);
                red_add_v4(out + cur * CCH + lane * 4, m);
                accA = make_float4(0.f, 0.f, 0.f, 0.f);
                accB = make_float4(0.f, 0.f, 0.f, 0.f);
                cur = s1;
            }
            accB.x += v[u + 1].x; accB.y += v[u + 1].y;
            accB.z += v[u + 1].z; accB.w += v[u + 1].w;
        }
    }
    for (; n < n1; n++, p += 32) {
        float4 v = __ldcs(p);
        int s = seg_at(batch, n, is64);
        if (s != cur) {
            float4 m = make_float4(accA.x + accB.x, accA.y + accB.y,
                                   accA.z + accB.z, accA.w + accB.w);
            red_add_v4(out + cur * CCH + lane * 4, m);
            accA = make_float4(0.f, 0.f, 0.f, 0.f);
            accB = make_float4(0.f, 0.f, 0.f, 0.f);
            cur = s;
        }
        accA.x += v.x; accA.y += v.y; accA.z += v.z; accA.w += v.w;
    }
    {
        float4 m = make_float4(accA.x + accB.x, accA.y + accB.y,
                               accA.z + accB.z, accA.w + accB.w);
        red_add_v4(out + cur * CCH + lane * 4, m);
    }
}

extern "C" void kernel_launch(void* const* d_in, const int* in_sizes, int n_in,
                              void* d_out, int out_size) {
    const float* x     = (const float*)d_in[0];   // [N, 128] fp32
    const void*  batch = d_in[1];                 // [N] int32/int64 sorted
    float* out = (float*)d_out;

    const int N = in_sizes[1];

    zero_out_kernel<<<(out_size / 4 + 255) / 256, 256>>>((float4*)out, out_size / 4);

    const int blocks = 148 * 12;                  // single wave at 12 blocks/SM
    const int nwarps = blocks * (128 / 32);
    seg_sum_kernel<<<blocks, 128>>>((const float4*)x, batch, out, N, nwarps);
}

// round 4
// speedup vs baseline: 1.1630x; 1.1630x over previous
#include <cuda_runtime.h>

// Pooling_83141976916902: degenerate softmax gate => pure sorted segment-sum.
//   out[g, :] = sum_{n : batch[n]==g} x[n, :],  N=1e6, C=128.
//
// R4 = revert to R1's memory configuration (best DRAM 77.6%, 87.2us kernel):
//   256-thread blocks, grid 148*8, U=8 plain __ldg batch loads.
// Keep from R2/R3 only the orthogonal wins:
//   - red.global.add.v4.f32 flush (1 op vs 4 scalar atomics)
//   - int32 indexing + incremented pointers (fewer regs/IMADs)
// R3 lesson: __ldcs is a de-optimization here (L1 23->39%, DRAM 75->64%).

#define CCH 128

__global__ void zero_out_kernel(float4* __restrict__ out, int n4) {
    int i = blockIdx.x * blockDim.x + threadIdx.x;
    if (i < n4) out[i] = make_float4(0.f, 0.f, 0.f, 0.f);
}

__device__ __forceinline__ int seg_at(const void* batch, int n, bool is64) {
    if (is64) return (int)__ldg(((const long long*)batch) + n);
    return __ldg(((const int*)batch) + n);
}

__device__ __forceinline__ void red_add_v4(float* addr, float4 v) {
    asm volatile("red.global.add.v4.f32 [%0], {%1, %2, %3, %4};"
                 :: "l"(addr), "f"(v.x), "f"(v.y), "f"(v.z), "f"(v.w)
                 : "memory");
}

__global__ __launch_bounds__(256) void seg_sum_kernel(
    const float4* __restrict__ x4,     // N rows x 32 float4
    const void*   __restrict__ batch,  // int32 or int64, sorted
    float*        __restrict__ out,    // [G * 128]
    int N, int nwarp_total)
{
    // dtype probe: odd int32 index mid-array. int64 -> high word == 0;
    // int32 -> sorted mid segment id != 0. In-bounds either way.
    const int probe = ((N >> 1) | 1);
    const bool is64 = (__ldg(((const int*)batch) + probe) == 0);

    const int gwarp = (blockIdx.x * blockDim.x + threadIdx.x) >> 5;
    const int lane  = threadIdx.x & 31;

    const int chunk = (N + nwarp_total - 1) / nwarp_total;
    int n0 = gwarp * chunk;
    int n1 = n0 + chunk;
    if (n1 > N) n1 = N;
    if (n0 >= n1) return;

    float4 acc = make_float4(0.f, 0.f, 0.f, 0.f);
    int cur = seg_at(batch, n0, is64);

    const float4* p = x4 + n0 * 32 + lane;

    int n = n0;
    constexpr int U = 8;

    for (; n + U <= n1; n += U, p += U * 32) {
        float4 v[U];
        int    s[U];
        #pragma unroll
        for (int u = 0; u < U; u++)
            v[u] = __ldg(p + u * 32);              // U independent DRAM loads
        #pragma unroll
        for (int u = 0; u < U; u++)
            s[u] = seg_at(batch, n + u, is64);     // L1 broadcast hits
        #pragma unroll
        for (int u = 0; u < U; u++) {
            if (s[u] != cur) {
                red_add_v4(out + cur * CCH + lane * 4, acc);
                acc = make_float4(0.f, 0.f, 0.f, 0.f);
                cur = s[u];
            }
            acc.x += v[u].x; acc.y += v[u].y;
            acc.z += v[u].z; acc.w += v[u].w;
        }
    }
    for (; n < n1; n++, p += 32) {
        float4 v = __ldg(p);
        int s = seg_at(batch, n, is64);
        if (s != cur) {
            red_add_v4(out + cur * CCH + lane * 4, acc);
            acc = make_float4(0.f, 0.f, 0.f, 0.f);
            cur = s;
        }
        acc.x += v.x; acc.y += v.y; acc.z += v.z; acc.w += v.w;
    }
    red_add_v4(out + cur * CCH + lane * 4, acc);
}

extern "C" void kernel_launch(void* const* d_in, const int* in_sizes, int n_in,
                              void* d_out, int out_size) {
    const float* x     = (const float*)d_in[0];   // [N, 128] fp32
    const void*  batch = d_in[1];                 // [N] int32/int64 sorted
    float* out = (float*)d_out;

    const int N = in_sizes[1];

    zero_out_kernel<<<(out_size / 4 + 255) / 256, 256>>>((float4*)out, out_size / 4);

    const int blocks = 148 * 8;                   // R1 config: best measured DRAM%
    const int nwarps = blocks * (256 / 32);
    seg_sum_kernel<<<blocks, 256>>>((const float4*)x, batch, out, N, nwarps);
}

// round 6
// speedup vs baseline: 1.2138x; 1.0436x over previous
#include <cuda_runtime.h>
#include <cstdint>

// Pooling_83141976916902: degenerate softmax gate => pure sorted segment-sum.
//   out[g, :] = sum_{n : batch[n]==g} x[n, :],  N=1e6, C=128.
//
// R6 = R5 with the missing <cstdint> include (compile fix only).
// cp.async.cg staging: limiter model = in-flight bytes/SM. LDGSTS holds
// in-flight data in smem (not registers), per-warp private double buffer,
// no barriers (lane-private 16B slots; wait_group is per-thread).

#define CCH 128
#define WPB 4            // warps per block (128 threads)
#define RPS 8            // rows per stage (8 x 512B = 4KB per warp-stage)

__global__ void zero_out_kernel(float4* __restrict__ out, int n4) {
    int i = blockIdx.x * blockDim.x + threadIdx.x;
    if (i < n4) out[i] = make_float4(0.f, 0.f, 0.f, 0.f);
}

__device__ __forceinline__ int seg_at(const void* batch, int n, bool is64) {
    if (is64) return (int)__ldg(((const long long*)batch) + n);
    return __ldg(((const int*)batch) + n);
}

__device__ __forceinline__ void red_add_v4(float* addr, float4 v) {
    asm volatile("red.global.add.v4.f32 [%0], {%1, %2, %3, %4};"
                 :: "l"(addr), "f"(v.x), "f"(v.y), "f"(v.z), "f"(v.w)
                 : "memory");
}

__device__ __forceinline__ void cp16(unsigned int saddr, const void* gptr) {
    asm volatile("cp.async.cg.shared.global [%0], [%1], 16;"
                 :: "r"(saddr), "l"(gptr));
}
__device__ __forceinline__ void cp_commit() {
    asm volatile("cp.async.commit_group;" ::: "memory");
}
template <int NREM>
__device__ __forceinline__ void cp_wait() {
    asm volatile("cp.async.wait_group %0;" :: "n"(NREM) : "memory");
}

__global__ __launch_bounds__(WPB * 32) void seg_sum_kernel(
    const float4* __restrict__ x4,     // N rows x 32 float4
    const void*   __restrict__ batch,  // int32 or int64, sorted
    float*        __restrict__ out,    // [G * 128]
    int N, int nwarp_total)
{
    __shared__ float4 buf[WPB][2][RPS][32];   // 32KB

    // dtype probe: odd int32 index mid-array. int64 -> high word == 0;
    // int32 -> sorted mid segment id != 0. In-bounds either way.
    const int probe = ((N >> 1) | 1);
    const bool is64 = (__ldg(((const int*)batch) + probe) == 0);

    const int gwarp = (blockIdx.x * blockDim.x + threadIdx.x) >> 5;
    const int warp  = threadIdx.x >> 5;
    const int lane  = threadIdx.x & 31;

    const int chunk = (N + nwarp_total - 1) / nwarp_total;
    int n0 = gwarp * chunk;
    int n1 = n0 + chunk;
    if (n1 > N) n1 = N;
    if (n0 >= n1) return;

    float4 acc = make_float4(0.f, 0.f, 0.f, 0.f);
    int cur = seg_at(batch, n0, is64);

    const float4* gp = x4 + n0 * 32 + lane;   // this lane's column, row n0
    const int rows = n1 - n0;
    const int T = rows & ~(RPS - 1);          // full-stage rows

    unsigned int sb[2];
    sb[0] = (unsigned int)__cvta_generic_to_shared(&buf[warp][0][0][lane]);
    sb[1] = (unsigned int)__cvta_generic_to_shared(&buf[warp][1][0][lane]);

    int issued = 0;
    #pragma unroll
    for (int s = 0; s < 2; s++) {
        if (issued + RPS <= T) {
            #pragma unroll
            for (int r = 0; r < RPS; r++)
                cp16(sb[s] + r * 512, gp + (issued + r) * 32);
            cp_commit();
            issued += RPS;
        }
    }

    for (int t = 0; t < T; t += RPS) {
        const int stg = (t / RPS) & 1;
        if (issued - t > RPS) cp_wait<1>();   // 2 groups out: wait oldest
        else                  cp_wait<0>();   // last group: wait all

        int s[RPS];
        #pragma unroll
        for (int r = 0; r < RPS; r++)
            s[r] = seg_at(batch, n0 + t + r, is64);   // L1 broadcast hits

        #pragma unroll
        for (int r = 0; r < RPS; r++) {
            float4 v = buf[warp][stg][r][lane];
            if (s[r] != cur) {
                red_add_v4(out + cur * CCH + lane * 4, acc);
                acc = make_float4(0.f, 0.f, 0.f, 0.f);
                cur = s[r];
            }
            acc.x += v.x; acc.y += v.y; acc.z += v.z; acc.w += v.w;
        }

        if (issued + RPS <= T) {              // refill the freed buffer
            #pragma unroll
            for (int r = 0; r < RPS; r++)
                cp16(sb[stg] + r * 512, gp + (issued + r) * 32);
            cp_commit();
            issued += RPS;
        }
    }

    for (int n = n0 + T; n < n1; n++) {       // tail rows
        float4 v = __ldg(gp + (n - n0) * 32);
        int s = seg_at(batch, n, is64);
        if (s != cur) {
            red_add_v4(out + cur * CCH + lane * 4, acc);
            acc = make_float4(0.f, 0.f, 0.f, 0.f);
            cur = s;
        }
        acc.x += v.x; acc.y += v.y; acc.z += v.z; acc.w += v.w;
    }
    red_add_v4(out + cur * CCH + lane * 4, acc);
}

extern "C" void kernel_launch(void* const* d_in, const int* in_sizes, int n_in,
                              void* d_out, int out_size) {
    const float* x     = (const float*)d_in[0];   // [N, 128] fp32
    const void*  batch = d_in[1];                 // [N] int32/int64 sorted
    float* out = (float*)d_out;

    const int N = in_sizes[1];

    zero_out_kernel<<<(out_size / 4 + 255) / 256, 256>>>((float4*)out, out_size / 4);

    const int blocks = 148 * 5;                   // single wave (smem 32KB/block)
    const int nwarps = blocks * WPB;
    seg_sum_kernel<<<blocks, WPB * 32>>>((const float4*)x, batch, out, N, nwarps);
}